// round 1
// baseline (speedup 1.0000x reference)
#include <cuda_runtime.h>

// Problem constants
#define BB 4
#define SS 8192
#define DD 512
#define HH 8
#define HDIM 64
#define RR 64
#define BSROWS (BB * SS)      // 32768
#define NCHUNK 16

// -------- scratch (static device globals; no allocation) --------
__device__ float g_q[BSROWS * DD];
__device__ float g_k[BSROWS * DD];
__device__ float g_v[BSROWS * DD];
__device__ float g_attn[BSROWS * DD];
__device__ float g_phiq[BB * HH * SS * RR];
__device__ float g_phik[BB * HH * SS * RR];
__device__ float g_kvp[BB * HH * NCHUNK * RR * HDIM];
__device__ float g_ksp[BB * HH * NCHUNK * RR];
__device__ float g_kv[BB * HH * RR * HDIM];
__device__ float g_ks[BB * HH * RR];

// ============================================================
// SGEMM: C[M,N] = A[M,K] @ B[K,N] + bias[N]   (all row-major)
// BM=128, BN=128, BK=8, 256 threads, 8x8 per thread.
// Requires M%128==0, N%128==0, K%8==0.
// ============================================================
__global__ __launch_bounds__(256) void sgemm_bias(
    const float* __restrict__ A, const float* __restrict__ Bm,
    const float* __restrict__ bias, float* __restrict__ C,
    int M, int N, int K)
{
    __shared__ float As[8][128];
    __shared__ float Bs[8][128];

    const int tid = threadIdx.x;
    const int bn = blockIdx.x, bm = blockIdx.y;

    const float* Ab = A + (size_t)bm * 128 * K;
    const float* Bb = Bm + bn * 128;

    const int arow = tid >> 1, ac4 = (tid & 1) * 4;
    const int brow = tid >> 5, bc4 = (tid & 31) * 4;
    const int ty = tid >> 4, tx = tid & 15;

    float acc[8][8];
#pragma unroll
    for (int i = 0; i < 8; i++)
#pragma unroll
        for (int j = 0; j < 8; j++) acc[i][j] = 0.f;

    for (int k0 = 0; k0 < K; k0 += 8) {
        float4 a = *(const float4*)&Ab[(size_t)arow * K + k0 + ac4];
        As[ac4 + 0][arow] = a.x;
        As[ac4 + 1][arow] = a.y;
        As[ac4 + 2][arow] = a.z;
        As[ac4 + 3][arow] = a.w;
        *(float4*)&Bs[brow][bc4] =
            *(const float4*)&Bb[(size_t)(k0 + brow) * N + bc4];
        __syncthreads();

#pragma unroll
        for (int kk = 0; kk < 8; kk++) {
            float4 a0 = *(float4*)&As[kk][ty * 8];
            float4 a1 = *(float4*)&As[kk][ty * 8 + 4];
            float4 b0 = *(float4*)&Bs[kk][tx * 8];
            float4 b1 = *(float4*)&Bs[kk][tx * 8 + 4];
            float ar[8] = {a0.x, a0.y, a0.z, a0.w, a1.x, a1.y, a1.z, a1.w};
            float br[8] = {b0.x, b0.y, b0.z, b0.w, b1.x, b1.y, b1.z, b1.w};
#pragma unroll
            for (int i = 0; i < 8; i++)
#pragma unroll
                for (int j = 0; j < 8; j++) acc[i][j] += ar[i] * br[j];
        }
        __syncthreads();
    }

    const int col = bn * 128 + tx * 8;
    float4 bi0 = *(const float4*)&bias[col];
    float4 bi1 = *(const float4*)&bias[col + 4];
#pragma unroll
    for (int i = 0; i < 8; i++) {
        size_t row = (size_t)bm * 128 + ty * 8 + i;
        float4 o0 = make_float4(acc[i][0] + bi0.x, acc[i][1] + bi0.y,
                                acc[i][2] + bi0.z, acc[i][3] + bi0.w);
        float4 o1 = make_float4(acc[i][4] + bi1.x, acc[i][5] + bi1.y,
                                acc[i][6] + bi1.z, acc[i][7] + bi1.w);
        *(float4*)&C[row * N + col] = o0;
        *(float4*)&C[row * N + col + 4] = o1;
    }
}

// ============================================================
// Sketch: for each (b,h,s):  z = gamma*Z[b,s,h,:] + beta  (64)
//   u = z@G1, w = z@G2, half = (1/8)*u*w, phi = half*half
// Z layout: [BS, D] (head h at cols h*64..); phi: [B,H,S,R]
// Block: (rowtile of 64 global rows) x (head). 256 threads.
// ============================================================
__global__ __launch_bounds__(256) void sketch_kernel(
    const float* __restrict__ Z,
    const float* __restrict__ G1, const float* __restrict__ G2,
    const float* __restrict__ gamma, const float* __restrict__ beta,
    float* __restrict__ phi)
{
    __shared__ float Zs[64][64];
    __shared__ float G1s[64 * 64];
    __shared__ float G2s[64 * 64];

    const int tid = threadIdx.x;
    const int h = blockIdx.y;
    const int row0 = blockIdx.x * 64;

    for (int i = tid; i < 1024; i += 256) {
        ((float4*)G1s)[i] = ((const float4*)G1)[i];
        ((float4*)G2s)[i] = ((const float4*)G2)[i];
    }
    const float g0 = gamma[0], b0 = beta[0];
    for (int i = tid; i < 1024; i += 256) {
        int r = i >> 4;
        int c4 = (i & 15) * 4;
        float4 z = *(const float4*)&Z[(size_t)(row0 + r) * DD + h * HDIM + c4];
        z.x = g0 * z.x + b0;
        z.y = g0 * z.y + b0;
        z.z = g0 * z.z + b0;
        z.w = g0 * z.w + b0;
        *(float4*)&Zs[r][c4] = z;
    }
    __syncthreads();

    const int tr = tid >> 4, tc = tid & 15;
    const int r0 = tr * 4, c0 = tc * 4;
    float au[4][4], aw[4][4];
#pragma unroll
    for (int i = 0; i < 4; i++)
#pragma unroll
        for (int j = 0; j < 4; j++) { au[i][j] = 0.f; aw[i][j] = 0.f; }

#pragma unroll 8
    for (int hd = 0; hd < 64; hd++) {
        float4 g1 = *(float4*)&G1s[hd * 64 + c0];
        float4 g2 = *(float4*)&G2s[hd * 64 + c0];
#pragma unroll
        for (int i = 0; i < 4; i++) {
            float z = Zs[r0 + i][hd];
            au[i][0] += z * g1.x; au[i][1] += z * g1.y;
            au[i][2] += z * g1.z; au[i][3] += z * g1.w;
            aw[i][0] += z * g2.x; aw[i][1] += z * g2.y;
            aw[i][2] += z * g2.z; aw[i][3] += z * g2.w;
        }
    }

    const int b = row0 / SS;
    const int sbase = row0 % SS;
    const float inv = 0.125f;  // 1/sqrt(64)
#pragma unroll
    for (int i = 0; i < 4; i++) {
        int s = sbase + r0 + i;
        float h0 = inv * au[i][0] * aw[i][0];
        float h1 = inv * au[i][1] * aw[i][1];
        float h2 = inv * au[i][2] * aw[i][2];
        float h3 = inv * au[i][3] * aw[i][3];
        float4 o = make_float4(h0 * h0, h1 * h1, h2 * h2, h3 * h3);
        *(float4*)&phi[(((size_t)b * HH + h) * SS + s) * RR + c0] = o;
    }
}

// ============================================================
// kv partial: kv[b,h,r,d] = sum_s phi_k[b,h,s,r]*v[b,s,h,d]
// ksum[b,h,r] = sum_s phi_k[b,h,s,r]     (chunked over S, deterministic)
// ============================================================
__global__ __launch_bounds__(256) void kvsum_kernel(
    const float* __restrict__ phik, const float* __restrict__ v,
    float* __restrict__ kvp, float* __restrict__ ksp)
{
    const int bh = blockIdx.y;
    const int chunk = blockIdx.x;
    const int b = bh >> 3, h = bh & 7;
    const int CS = SS / NCHUNK;  // 512

    __shared__ float Ps[32][64];
    __shared__ float Vs[32][64];

    const int tid = threadIdx.x;
    const int tr = tid >> 4, tc = tid & 15;
    const int r0 = tr * 4, d0 = tc * 4;

    float acc[4][4];
#pragma unroll
    for (int i = 0; i < 4; i++)
#pragma unroll
        for (int j = 0; j < 4; j++) acc[i][j] = 0.f;
    float ks = 0.f;

    const int s0 = chunk * CS;
    for (int st = 0; st < CS; st += 32) {
        for (int i = tid; i < 512; i += 256) {
            int row = i >> 4;
            int c4 = (i & 15) * 4;
            *(float4*)&Ps[row][c4] =
                *(const float4*)&phik[((size_t)bh * SS + s0 + st + row) * RR + c4];
            *(float4*)&Vs[row][c4] =
                *(const float4*)&v[((size_t)b * SS + s0 + st + row) * DD + h * HDIM + c4];
        }
        __syncthreads();
#pragma unroll 8
        for (int ss = 0; ss < 32; ss++) {
            float4 p = *(float4*)&Ps[ss][r0];
            float4 vv = *(float4*)&Vs[ss][d0];
            acc[0][0] += p.x * vv.x; acc[0][1] += p.x * vv.y;
            acc[0][2] += p.x * vv.z; acc[0][3] += p.x * vv.w;
            acc[1][0] += p.y * vv.x; acc[1][1] += p.y * vv.y;
            acc[1][2] += p.y * vv.z; acc[1][3] += p.y * vv.w;
            acc[2][0] += p.z * vv.x; acc[2][1] += p.z * vv.y;
            acc[2][2] += p.z * vv.z; acc[2][3] += p.z * vv.w;
            acc[3][0] += p.w * vv.x; acc[3][1] += p.w * vv.y;
            acc[3][2] += p.w * vv.z; acc[3][3] += p.w * vv.w;
        }
        if (tid < 64) {
#pragma unroll
            for (int ss = 0; ss < 32; ss++) ks += Ps[ss][tid];
        }
        __syncthreads();
    }

    float* kvout = kvp + ((size_t)bh * NCHUNK + chunk) * (RR * HDIM);
#pragma unroll
    for (int i = 0; i < 4; i++)
        *(float4*)&kvout[(r0 + i) * HDIM + d0] =
            make_float4(acc[i][0], acc[i][1], acc[i][2], acc[i][3]);
    if (tid < 64) ksp[((size_t)bh * NCHUNK + chunk) * RR + tid] = ks;
}

__global__ void reduce_kernel(const float* __restrict__ kvp,
                              const float* __restrict__ ksp,
                              float* __restrict__ kv, float* __restrict__ ks)
{
    const int idx = blockIdx.x * 256 + threadIdx.x;
    const int total_kv = BB * HH * RR * HDIM;  // 131072
    if (idx < total_kv) {
        int bh = idx >> 12, e = idx & 4095;
        float s = 0.f;
#pragma unroll
        for (int c = 0; c < NCHUNK; c++)
            s += kvp[((size_t)bh * NCHUNK + c) * 4096 + e];
        kv[idx] = s;
    } else if (idx < total_kv + BB * HH * RR) {
        int j = idx - total_kv;
        int bh = j >> 6, r = j & 63;
        float s = 0.f;
#pragma unroll
        for (int c = 0; c < NCHUNK; c++)
            s += ksp[((size_t)bh * NCHUNK + c) * RR + r];
        ks[j] = s;
    }
}

// ============================================================
// attn[b,s,h,d] = (phi_q[b,h,s,:] @ kv[b,h,:,d]) / (phi_q . ksum + eps)
// Block: (stile of 32 rows) x (bh). 256 threads.
// ============================================================
__global__ __launch_bounds__(256) void attn_out_kernel(
    const float* __restrict__ phiq, const float* __restrict__ kv,
    const float* __restrict__ ks, float* __restrict__ attn)
{
    const int bh = blockIdx.y;
    const int stile = blockIdx.x;
    const int b = bh >> 3, h = bh & 7;

    __shared__ float KVs[4096];
    __shared__ float KSs[64];
    __shared__ float Ps[32 * 65];
    __shared__ float Dens[32];

    const int tid = threadIdx.x;
    const int s0 = stile * 32;

    for (int i = tid; i < 1024; i += 256)
        ((float4*)KVs)[i] = ((const float4*)(kv + (size_t)bh * 4096))[i];
    if (tid < 64) KSs[tid] = ks[bh * RR + tid];
    for (int i = tid; i < 2048; i += 256) {
        int row = i >> 6, c = i & 63;
        Ps[row * 65 + c] = phiq[((size_t)bh * SS + s0 + row) * RR + c];
    }
    __syncthreads();

    if (tid < 32) {
        float dsum = 0.f;
#pragma unroll
        for (int r = 0; r < 64; r++) dsum += Ps[tid * 65 + r] * KSs[r];
        Dens[tid] = dsum + 1e-6f;
    }
    __syncthreads();

    const int d = tid & 63, g = tid >> 6;
    for (int rr = g; rr < 32; rr += 4) {
        float num = 0.f;
#pragma unroll
        for (int r = 0; r < 64; r++) num += Ps[rr * 65 + r] * KVs[r * 64 + d];
        attn[((size_t)b * SS + s0 + rr) * DD + h * HDIM + d] = num / Dens[rr];
    }
}

// ============================================================
// launch
// ============================================================
extern "C" void kernel_launch(void* const* d_in, const int* in_sizes, int n_in,
                              void* d_out, int out_size)
{
    const float* x       = (const float*)d_in[0];
    const float* Wq      = (const float*)d_in[1];
    const float* bq      = (const float*)d_in[2];
    const float* Wk      = (const float*)d_in[3];
    const float* bk      = (const float*)d_in[4];
    const float* Wv      = (const float*)d_in[5];
    const float* bv      = (const float*)d_in[6];
    const float* Wp      = (const float*)d_in[7];
    const float* bp      = (const float*)d_in[8];
    const float* gamma_q = (const float*)d_in[9];
    const float* beta_q  = (const float*)d_in[10];
    const float* gamma_k = (const float*)d_in[11];
    const float* beta_k  = (const float*)d_in[12];
    const float* qG1     = (const float*)d_in[13];
    const float* qG2     = (const float*)d_in[14];
    const float* kG1     = (const float*)d_in[15];
    const float* kG2     = (const float*)d_in[16];
    float* out = (float*)d_out;

    float *p_q, *p_k, *p_v, *p_attn, *p_phiq, *p_phik, *p_kvp, *p_ksp, *p_kv, *p_ks;
    cudaGetSymbolAddress((void**)&p_q, g_q);
    cudaGetSymbolAddress((void**)&p_k, g_k);
    cudaGetSymbolAddress((void**)&p_v, g_v);
    cudaGetSymbolAddress((void**)&p_attn, g_attn);
    cudaGetSymbolAddress((void**)&p_phiq, g_phiq);
    cudaGetSymbolAddress((void**)&p_phik, g_phik);
    cudaGetSymbolAddress((void**)&p_kvp, g_kvp);
    cudaGetSymbolAddress((void**)&p_ksp, g_ksp);
    cudaGetSymbolAddress((void**)&p_kv, g_kv);
    cudaGetSymbolAddress((void**)&p_ks, g_ks);

    dim3 gemm_grid(DD / 128, BSROWS / 128);  // (4, 256)
    sgemm_bias<<<gemm_grid, 256>>>(x, Wq, bq, p_q, BSROWS, DD, DD);
    sgemm_bias<<<gemm_grid, 256>>>(x, Wk, bk, p_k, BSROWS, DD, DD);
    sgemm_bias<<<gemm_grid, 256>>>(x, Wv, bv, p_v, BSROWS, DD, DD);

    dim3 sk_grid(BSROWS / 64, HH);  // (512, 8)
    sketch_kernel<<<sk_grid, 256>>>(p_q, qG1, qG2, gamma_q, beta_q, p_phiq);
    sketch_kernel<<<sk_grid, 256>>>(p_k, kG1, kG2, gamma_k, beta_k, p_phik);

    kvsum_kernel<<<dim3(NCHUNK, BB * HH), 256>>>(p_phik, p_v, p_kvp, p_ksp);

    int red_total = BB * HH * RR * HDIM + BB * HH * RR;
    reduce_kernel<<<(red_total + 255) / 256, 256>>>(p_kvp, p_ksp, p_kv, p_ks);

    attn_out_kernel<<<dim3(SS / 32, BB * HH), 256>>>(p_phiq, p_kv, p_ks, p_attn);

    sgemm_bias<<<gemm_grid, 256>>>(p_attn, Wp, bp, out, BSROWS, DD, DD);
}

// round 3
// speedup vs baseline: 1.5173x; 1.5173x over previous
#include <cuda_runtime.h>
#include <cuda_bf16.h>
#include <cstdint>

// Problem constants
#define BB 4
#define SS 8192
#define DD 512
#define HH 8
#define HDIM 64
#define RR 64
#define BSROWS (BB * SS)      // 32768
#define NCHUNK 16

// -------- scratch (static device globals; no allocation) --------
__device__ float g_q[BSROWS * DD];
__device__ float g_k[BSROWS * DD];
__device__ float g_v[BSROWS * DD];
__device__ float g_attn[BSROWS * DD];
__device__ float g_phiq[BB * HH * SS * RR];
__device__ float g_phik[BB * HH * SS * RR];
__device__ float g_kvp[BB * HH * NCHUNK * RR * HDIM];
__device__ float g_ksp[BB * HH * NCHUNK * RR];
__device__ float g_kv[BB * HH * RR * HDIM];
__device__ float g_ks[BB * HH * RR];
__device__ float g_wt[4][DD * DD];   // transposed weights

// ============================================================
// helpers
// ============================================================
__device__ __forceinline__ uint32_t smem_to_u32(const void* p) {
    uint32_t a;
    asm("{ .reg .u64 t; cvta.to.shared.u64 t, %1; cvt.u32.u64 %0, t; }"
        : "=r"(a) : "l"(p));
    return a;
}

__device__ __forceinline__ void ldsm4(uint32_t& r0, uint32_t& r1,
                                      uint32_t& r2, uint32_t& r3,
                                      uint32_t addr) {
    asm volatile("ldmatrix.sync.aligned.m8n8.x4.shared.b16 {%0,%1,%2,%3}, [%4];"
                 : "=r"(r0), "=r"(r1), "=r"(r2), "=r"(r3) : "r"(addr));
}

__device__ __forceinline__ void mma16816(float* d, const uint32_t* a,
                                         const uint32_t* b) {
    asm volatile(
        "mma.sync.aligned.m16n8k16.row.col.f32.bf16.bf16.f32 "
        "{%0,%1,%2,%3}, {%4,%5,%6,%7}, {%8,%9}, {%0,%1,%2,%3};"
        : "+f"(d[0]), "+f"(d[1]), "+f"(d[2]), "+f"(d[3])
        : "r"(a[0]), "r"(a[1]), "r"(a[2]), "r"(a[3]), "r"(b[0]), "r"(b[1]));
}

__device__ __forceinline__ void split4(float4 v, uint2& hi, uint2& lo) {
    __nv_bfloat16 h0 = __float2bfloat16_rn(v.x), h1 = __float2bfloat16_rn(v.y);
    __nv_bfloat16 h2 = __float2bfloat16_rn(v.z), h3 = __float2bfloat16_rn(v.w);
    float r0 = v.x - __bfloat162float(h0), r1 = v.y - __bfloat162float(h1);
    float r2 = v.z - __bfloat162float(h2), r3 = v.w - __bfloat162float(h3);
    __nv_bfloat16 l0 = __float2bfloat16_rn(r0), l1 = __float2bfloat16_rn(r1);
    __nv_bfloat16 l2 = __float2bfloat16_rn(r2), l3 = __float2bfloat16_rn(r3);
    hi.x = ((uint32_t)__bfloat16_as_ushort(h1) << 16) | __bfloat16_as_ushort(h0);
    hi.y = ((uint32_t)__bfloat16_as_ushort(h3) << 16) | __bfloat16_as_ushort(h2);
    lo.x = ((uint32_t)__bfloat16_as_ushort(l1) << 16) | __bfloat16_as_ushort(l0);
    lo.y = ((uint32_t)__bfloat16_as_ushort(l3) << 16) | __bfloat16_as_ushort(l2);
}

// ============================================================
// Transpose 512x512: Wt[n][k] = W[k][n]
// ============================================================
__global__ __launch_bounds__(256) void transpose512(
    const float* __restrict__ W, float* __restrict__ Wt)
{
    __shared__ float t[32][33];
    int bx = blockIdx.x * 32, by = blockIdx.y * 32;
    int x = threadIdx.x & 31, y = threadIdx.x >> 5;  // 32x8
    for (int i = y; i < 32; i += 8) t[i][x] = W[(size_t)(by + i) * DD + bx + x];
    __syncthreads();
    for (int i = y; i < 32; i += 8) Wt[(size_t)(bx + i) * DD + by + x] = t[x][i];
}

// ============================================================
// Tensor-core (mma.sync bf16 3-pass split) GEMM:
//   C[M,512] = A[M,512] @ W + bias ;  Wt = W^T ([n][k], k contiguous)
// Tile 128x128, BK=32, 8 warps (4x2), warp tile 32x64,
// double-buffered smem stages of {Ahi, Alo, Bhi, Blo}.
// ============================================================
#define BKC 32
#define NKCH (DD / BKC)          // 16
#define ST_AHI 0
#define ST_ALO 8192
#define ST_BHI 16384
#define ST_BLO 24576
#define ST_BYTES 32768
#define GEMM_SMEM (2 * ST_BYTES)   // 65536
// swizzled byte offset inside a tile: row stride 64B, 16B chunk xor row&3
#define SWZ(row, chunk) ((uint32_t)((row) * 64 + ((((chunk) ^ ((row) & 3))) << 4)))

__global__ __launch_bounds__(256, 1) void mma_gemm(
    const float* __restrict__ A, const float* __restrict__ Wt,
    const float* __restrict__ bias, float* __restrict__ C)
{
    extern __shared__ char smem[];
    const uint32_t sb = smem_to_u32(smem);

    const int tid = threadIdx.x;
    const int wid = tid >> 5, lane = tid & 31;
    const int bn = blockIdx.x, bm = blockIdx.y;
    const int warp_m = wid >> 1, warp_n = wid & 1;

    const float* Abase = A + (size_t)bm * 128 * DD;
    const float* Bbase = Wt + (size_t)bn * 128 * DD;

    // loader mapping: 8 threads per row (float4 each), 32 rows/sweep, 4 sweeps
    const int lrow = tid >> 3;
    const int kg = tid & 7;
    const int lchunk = kg >> 1;
    const int lsub = (kg & 1) * 8;

    float acc[2][8][4];
#pragma unroll
    for (int i = 0; i < 2; i++)
#pragma unroll
        for (int j = 0; j < 8; j++)
#pragma unroll
            for (int e = 0; e < 4; e++) acc[i][j][e] = 0.f;

    // ldmatrix lane-address components
    const int mat = lane >> 3, mr = lane & 7;
    const int a_row_b = warp_m * 32 + (mat & 1) * 8 + mr;   // + im*16
    const int b_row_b = warp_n * 64 + (mat & 1) * 8 + mr;   // + j16*16
    const int mchunk = mat >> 1;                            // + kk*2

    // ---- prologue: load chunk 0 into stage 0 ----
    {
        char* st = smem;
#pragma unroll
        for (int sw = 0; sw < 4; sw++) {
            const int row = sw * 32 + lrow;
            float4 va = *(const float4*)&Abase[(size_t)row * DD + kg * 4];
            float4 vb = *(const float4*)&Bbase[(size_t)row * DD + kg * 4];
            uint2 hi, lo;
            split4(va, hi, lo);
            *(uint2*)(st + ST_AHI + SWZ(row, lchunk) + lsub) = hi;
            *(uint2*)(st + ST_ALO + SWZ(row, lchunk) + lsub) = lo;
            split4(vb, hi, lo);
            *(uint2*)(st + ST_BHI + SWZ(row, lchunk) + lsub) = hi;
            *(uint2*)(st + ST_BLO + SWZ(row, lchunk) + lsub) = lo;
        }
    }
    __syncthreads();

    for (int c = 0; c < NKCH; c++) {
        const int p = c & 1;
        const uint32_t stg = sb + p * ST_BYTES;

        // issue next chunk's global loads early
        float4 ra[4], rb[4];
        if (c + 1 < NKCH) {
            const int k0 = (c + 1) * BKC;
#pragma unroll
            for (int sw = 0; sw < 4; sw++) {
                const int row = sw * 32 + lrow;
                ra[sw] = *(const float4*)&Abase[(size_t)row * DD + k0 + kg * 4];
                rb[sw] = *(const float4*)&Bbase[(size_t)row * DD + k0 + kg * 4];
            }
        }

        // ---- compute chunk c: two k16 sub-steps ----
#pragma unroll
        for (int kk = 0; kk < 2; kk++) {
            uint32_t ahi[2][4], alo[2][4], bhi[8][2], blo[8][2];
#pragma unroll
            for (int im = 0; im < 2; im++) {
                const int row = a_row_b + im * 16;
                const int ch = kk * 2 + mchunk;
                ldsm4(ahi[im][0], ahi[im][1], ahi[im][2], ahi[im][3],
                      stg + ST_AHI + SWZ(row, ch));
                ldsm4(alo[im][0], alo[im][1], alo[im][2], alo[im][3],
                      stg + ST_ALO + SWZ(row, ch));
            }
#pragma unroll
            for (int j16 = 0; j16 < 4; j16++) {
                const int row = b_row_b + j16 * 16;
                const int ch = kk * 2 + mchunk;
                uint32_t r0, r1, r2, r3;
                ldsm4(r0, r1, r2, r3, stg + ST_BHI + SWZ(row, ch));
                bhi[j16 * 2][0] = r0; bhi[j16 * 2][1] = r2;
                bhi[j16 * 2 + 1][0] = r1; bhi[j16 * 2 + 1][1] = r3;
                ldsm4(r0, r1, r2, r3, stg + ST_BLO + SWZ(row, ch));
                blo[j16 * 2][0] = r0; blo[j16 * 2][1] = r2;
                blo[j16 * 2 + 1][0] = r1; blo[j16 * 2 + 1][1] = r3;
            }
#pragma unroll
            for (int im = 0; im < 2; im++)
#pragma unroll
                for (int t = 0; t < 8; t++) {
                    mma16816(acc[im][t], ahi[im], bhi[t]);
                    mma16816(acc[im][t], ahi[im], blo[t]);
                    mma16816(acc[im][t], alo[im], bhi[t]);
                }
        }

        // ---- store next chunk into the other stage ----
        if (c + 1 < NKCH) {
            char* st = smem + (1 - p) * ST_BYTES;
#pragma unroll
            for (int sw = 0; sw < 4; sw++) {
                const int row = sw * 32 + lrow;
                uint2 hi, lo;
                split4(ra[sw], hi, lo);
                *(uint2*)(st + ST_AHI + SWZ(row, lchunk) + lsub) = hi;
                *(uint2*)(st + ST_ALO + SWZ(row, lchunk) + lsub) = lo;
                split4(rb[sw], hi, lo);
                *(uint2*)(st + ST_BHI + SWZ(row, lchunk) + lsub) = hi;
                *(uint2*)(st + ST_BLO + SWZ(row, lchunk) + lsub) = lo;
            }
        }
        __syncthreads();
    }

    // ---- epilogue: add bias, store fp32 ----
    const int erow = lane >> 2, ecol = (lane & 3) * 2;
#pragma unroll
    for (int im = 0; im < 2; im++) {
        const size_t row0 = (size_t)bm * 128 + warp_m * 32 + im * 16 + erow;
#pragma unroll
        for (int t = 0; t < 8; t++) {
            const int col = bn * 128 + warp_n * 64 + t * 8 + ecol;
            float2 b2 = *(const float2*)&bias[col];
            float2 o0 = make_float2(acc[im][t][0] + b2.x, acc[im][t][1] + b2.y);
            float2 o1 = make_float2(acc[im][t][2] + b2.x, acc[im][t][3] + b2.y);
            *(float2*)&C[row0 * DD + col] = o0;
            *(float2*)&C[(row0 + 8) * DD + col] = o1;
        }
    }
}

// ============================================================
// Sketch: z = gamma*Z + beta; u=z@G1, w=z@G2, phi=((1/8)u*w)^2
// ============================================================
__global__ __launch_bounds__(256) void sketch_kernel(
    const float* __restrict__ Z,
    const float* __restrict__ G1, const float* __restrict__ G2,
    const float* __restrict__ gamma, const float* __restrict__ beta,
    float* __restrict__ phi)
{
    __shared__ float Zs[64][64];
    __shared__ float G1s[64 * 64];
    __shared__ float G2s[64 * 64];

    const int tid = threadIdx.x;
    const int h = blockIdx.y;
    const int row0 = blockIdx.x * 64;

    for (int i = tid; i < 1024; i += 256) {
        ((float4*)G1s)[i] = ((const float4*)G1)[i];
        ((float4*)G2s)[i] = ((const float4*)G2)[i];
    }
    const float g0 = gamma[0], b0 = beta[0];
    for (int i = tid; i < 1024; i += 256) {
        int r = i >> 4;
        int c4 = (i & 15) * 4;
        float4 z = *(const float4*)&Z[(size_t)(row0 + r) * DD + h * HDIM + c4];
        z.x = g0 * z.x + b0;
        z.y = g0 * z.y + b0;
        z.z = g0 * z.z + b0;
        z.w = g0 * z.w + b0;
        *(float4*)&Zs[r][c4] = z;
    }
    __syncthreads();

    const int tr = tid >> 4, tc = tid & 15;
    const int r0 = tr * 4, c0 = tc * 4;
    float au[4][4], aw[4][4];
#pragma unroll
    for (int i = 0; i < 4; i++)
#pragma unroll
        for (int j = 0; j < 4; j++) { au[i][j] = 0.f; aw[i][j] = 0.f; }

#pragma unroll 8
    for (int hd = 0; hd < 64; hd++) {
        float4 g1 = *(float4*)&G1s[hd * 64 + c0];
        float4 g2 = *(float4*)&G2s[hd * 64 + c0];
#pragma unroll
        for (int i = 0; i < 4; i++) {
            float z = Zs[r0 + i][hd];
            au[i][0] += z * g1.x; au[i][1] += z * g1.y;
            au[i][2] += z * g1.z; au[i][3] += z * g1.w;
            aw[i][0] += z * g2.x; aw[i][1] += z * g2.y;
            aw[i][2] += z * g2.z; aw[i][3] += z * g2.w;
        }
    }

    const int b = row0 / SS;
    const int sbase = row0 % SS;
    const float inv = 0.125f;
#pragma unroll
    for (int i = 0; i < 4; i++) {
        int s = sbase + r0 + i;
        float h0 = inv * au[i][0] * aw[i][0];
        float h1 = inv * au[i][1] * aw[i][1];
        float h2 = inv * au[i][2] * aw[i][2];
        float h3 = inv * au[i][3] * aw[i][3];
        float4 o = make_float4(h0 * h0, h1 * h1, h2 * h2, h3 * h3);
        *(float4*)&phi[(((size_t)b * HH + h) * SS + s) * RR + c0] = o;
    }
}

// ============================================================
// kv partial sums over S chunks
// ============================================================
__global__ __launch_bounds__(256) void kvsum_kernel(
    const float* __restrict__ phik, const float* __restrict__ v,
    float* __restrict__ kvp, float* __restrict__ ksp)
{
    const int bh = blockIdx.y;
    const int chunk = blockIdx.x;
    const int b = bh >> 3, h = bh & 7;
    const int CS = SS / NCHUNK;

    __shared__ float Ps[32][64];
    __shared__ float Vs[32][64];

    const int tid = threadIdx.x;
    const int tr = tid >> 4, tc = tid & 15;
    const int r0 = tr * 4, d0 = tc * 4;

    float acc[4][4];
#pragma unroll
    for (int i = 0; i < 4; i++)
#pragma unroll
        for (int j = 0; j < 4; j++) acc[i][j] = 0.f;
    float ks = 0.f;

    const int s0 = chunk * CS;
    for (int st = 0; st < CS; st += 32) {
        for (int i = tid; i < 512; i += 256) {
            int row = i >> 4;
            int c4 = (i & 15) * 4;
            *(float4*)&Ps[row][c4] =
                *(const float4*)&phik[((size_t)bh * SS + s0 + st + row) * RR + c4];
            *(float4*)&Vs[row][c4] =
                *(const float4*)&v[((size_t)b * SS + s0 + st + row) * DD + h * HDIM + c4];
        }
        __syncthreads();
#pragma unroll 8
        for (int ss = 0; ss < 32; ss++) {
            float4 p = *(float4*)&Ps[ss][r0];
            float4 vv = *(float4*)&Vs[ss][d0];
            acc[0][0] += p.x * vv.x; acc[0][1] += p.x * vv.y;
            acc[0][2] += p.x * vv.z; acc[0][3] += p.x * vv.w;
            acc[1][0] += p.y * vv.x; acc[1][1] += p.y * vv.y;
            acc[1][2] += p.y * vv.z; acc[1][3] += p.y * vv.w;
            acc[2][0] += p.z * vv.x; acc[2][1] += p.z * vv.y;
            acc[2][2] += p.z * vv.z; acc[2][3] += p.z * vv.w;
            acc[3][0] += p.w * vv.x; acc[3][1] += p.w * vv.y;
            acc[3][2] += p.w * vv.z; acc[3][3] += p.w * vv.w;
        }
        if (tid < 64) {
#pragma unroll
            for (int ss = 0; ss < 32; ss++) ks += Ps[ss][tid];
        }
        __syncthreads();
    }

    float* kvout = kvp + ((size_t)bh * NCHUNK + chunk) * (RR * HDIM);
#pragma unroll
    for (int i = 0; i < 4; i++)
        *(float4*)&kvout[(r0 + i) * HDIM + d0] =
            make_float4(acc[i][0], acc[i][1], acc[i][2], acc[i][3]);
    if (tid < 64) ksp[((size_t)bh * NCHUNK + chunk) * RR + tid] = ks;
}

__global__ void reduce_kernel(const float* __restrict__ kvp,
                              const float* __restrict__ ksp,
                              float* __restrict__ kv, float* __restrict__ ks)
{
    const int idx = blockIdx.x * 256 + threadIdx.x;
    const int total_kv = BB * HH * RR * HDIM;
    if (idx < total_kv) {
        int bh = idx >> 12, e = idx & 4095;
        float s = 0.f;
#pragma unroll
        for (int c = 0; c < NCHUNK; c++)
            s += kvp[((size_t)bh * NCHUNK + c) * 4096 + e];
        kv[idx] = s;
    } else if (idx < total_kv + BB * HH * RR) {
        int j = idx - total_kv;
        int bh = j >> 6, r = j & 63;
        float s = 0.f;
#pragma unroll
        for (int c = 0; c < NCHUNK; c++)
            s += ksp[((size_t)bh * NCHUNK + c) * RR + r];
        ks[j] = s;
    }
}

// ============================================================
// attn output
// ============================================================
__global__ __launch_bounds__(256) void attn_out_kernel(
    const float* __restrict__ phiq, const float* __restrict__ kv,
    const float* __restrict__ ks, float* __restrict__ attn)
{
    const int bh = blockIdx.y;
    const int stile = blockIdx.x;
    const int b = bh >> 3, h = bh & 7;

    __shared__ float KVs[4096];
    __shared__ float KSs[64];
    __shared__ float Ps[32 * 65];
    __shared__ float Dens[32];

    const int tid = threadIdx.x;
    const int s0 = stile * 32;

    for (int i = tid; i < 1024; i += 256)
        ((float4*)KVs)[i] = ((const float4*)(kv + (size_t)bh * 4096))[i];
    if (tid < 64) KSs[tid] = ks[bh * RR + tid];
    for (int i = tid; i < 2048; i += 256) {
        int row = i >> 6, c = i & 63;
        Ps[row * 65 + c] = phiq[((size_t)bh * SS + s0 + row) * RR + c];
    }
    __syncthreads();

    if (tid < 32) {
        float dsum = 0.f;
#pragma unroll
        for (int r = 0; r < 64; r++) dsum += Ps[tid * 65 + r] * KSs[r];
        Dens[tid] = dsum + 1e-6f;
    }
    __syncthreads();

    const int d = tid & 63, g = tid >> 6;
    for (int rr = g; rr < 32; rr += 4) {
        float num = 0.f;
#pragma unroll
        for (int r = 0; r < 64; r++) num += Ps[rr * 65 + r] * KVs[r * 64 + d];
        attn[((size_t)b * SS + s0 + rr) * DD + h * HDIM + d] = num / Dens[rr];
    }
}

// ============================================================
// launch
// ============================================================
extern "C" void kernel_launch(void* const* d_in, const int* in_sizes, int n_in,
                              void* d_out, int out_size)
{
    const float* x       = (const float*)d_in[0];
    const float* Wq      = (const float*)d_in[1];
    const float* bq      = (const float*)d_in[2];
    const float* Wk      = (const float*)d_in[3];
    const float* bk      = (const float*)d_in[4];
    const float* Wv      = (const float*)d_in[5];
    const float* bv      = (const float*)d_in[6];
    const float* Wp      = (const float*)d_in[7];
    const float* bp      = (const float*)d_in[8];
    const float* gamma_q = (const float*)d_in[9];
    const float* beta_q  = (const float*)d_in[10];
    const float* gamma_k = (const float*)d_in[11];
    const float* beta_k  = (const float*)d_in[12];
    const float* qG1     = (const float*)d_in[13];
    const float* qG2     = (const float*)d_in[14];
    const float* kG1     = (const float*)d_in[15];
    const float* kG2     = (const float*)d_in[16];
    float* out = (float*)d_out;

    float *p_q, *p_k, *p_v, *p_attn, *p_phiq, *p_phik, *p_kvp, *p_ksp, *p_kv, *p_ks, *p_wt;
    cudaGetSymbolAddress((void**)&p_q, g_q);
    cudaGetSymbolAddress((void**)&p_k, g_k);
    cudaGetSymbolAddress((void**)&p_v, g_v);
    cudaGetSymbolAddress((void**)&p_attn, g_attn);
    cudaGetSymbolAddress((void**)&p_phiq, g_phiq);
    cudaGetSymbolAddress((void**)&p_phik, g_phik);
    cudaGetSymbolAddress((void**)&p_kvp, g_kvp);
    cudaGetSymbolAddress((void**)&p_ksp, g_ksp);
    cudaGetSymbolAddress((void**)&p_kv, g_kv);
    cudaGetSymbolAddress((void**)&p_ks, g_ks);
    cudaGetSymbolAddress((void**)&p_wt, g_wt);

    cudaFuncSetAttribute(mma_gemm, cudaFuncAttributeMaxDynamicSharedMemorySize,
                         GEMM_SMEM);

    // transpose all 4 weight matrices (B operand must be [n][k])
    dim3 tg(16, 16);
    transpose512<<<tg, 256>>>(Wq, p_wt + 0 * DD * DD);
    transpose512<<<tg, 256>>>(Wk, p_wt + 1 * DD * DD);
    transpose512<<<tg, 256>>>(Wv, p_wt + 2 * DD * DD);
    transpose512<<<tg, 256>>>(Wp, p_wt + 3 * DD * DD);

    dim3 gg(DD / 128, BSROWS / 128);  // (4, 256)
    mma_gemm<<<gg, 256, GEMM_SMEM>>>(x, p_wt + 0 * DD * DD, bq, p_q);
    mma_gemm<<<gg, 256, GEMM_SMEM>>>(x, p_wt + 1 * DD * DD, bk, p_k);
    mma_gemm<<<gg, 256, GEMM_SMEM>>>(x, p_wt + 2 * DD * DD, bv, p_v);

    dim3 sk_grid(BSROWS / 64, HH);
    sketch_kernel<<<sk_grid, 256>>>(p_q, qG1, qG2, gamma_q, beta_q, p_phiq);
    sketch_kernel<<<sk_grid, 256>>>(p_k, kG1, kG2, gamma_k, beta_k, p_phik);

    kvsum_kernel<<<dim3(NCHUNK, BB * HH), 256>>>(p_phik, p_v, p_kvp, p_ksp);

    int red_total = BB * HH * RR * HDIM + BB * HH * RR;
    reduce_kernel<<<(red_total + 255) / 256, 256>>>(p_kvp, p_ksp, p_kv, p_ks);

    attn_out_kernel<<<dim3(SS / 32, BB * HH), 256>>>(p_phiq, p_kv, p_ks, p_attn);

    mma_gemm<<<gg, 256, GEMM_SMEM>>>(p_attn, p_wt + 3 * DD * DD, bp, out);
}

// round 4
// speedup vs baseline: 1.8080x; 1.1916x over previous
#include <cuda_runtime.h>
#include <cuda_bf16.h>
#include <cstdint>

// Problem constants
#define BB 4
#define SS 8192
#define DD 512
#define HH 8
#define HDIM 64
#define RR 64
#define BSROWS (BB * SS)      // 32768
#define NCHUNK 16

// -------- scratch (static device globals; no allocation) --------
__device__ float g_q[BSROWS * DD];
__device__ float g_k[BSROWS * DD];
__device__ float g_v[BSROWS * DD];
__device__ float g_phiq[BB * HH * SS * RR];
__device__ float g_phik[BB * HH * SS * RR];
__device__ float g_kvp[BB * HH * NCHUNK * RR * HDIM];
__device__ float g_ksp[BB * HH * NCHUNK * RR];
__device__ float g_kv[BB * HH * RR * HDIM];
__device__ float g_ks[BB * HH * RR];
__device__ __nv_bfloat16 g_xhi[BSROWS * DD];
__device__ __nv_bfloat16 g_xlo[BSROWS * DD];
__device__ __nv_bfloat16 g_ahi[BSROWS * DD];   // attn output hi
__device__ __nv_bfloat16 g_alo[BSROWS * DD];   // attn output lo
__device__ __nv_bfloat16 g_wthi[4 * DD * DD];  // [2048][512]: Wq^T,Wk^T,Wv^T,Wp^T
__device__ __nv_bfloat16 g_wtlo[4 * DD * DD];
__device__ float g_biasqkv[3 * DD];

// ============================================================
// helpers
// ============================================================
__device__ __forceinline__ uint32_t smem_to_u32(const void* p) {
    uint32_t a;
    asm("{ .reg .u64 t; cvta.to.shared.u64 t, %1; cvt.u32.u64 %0, t; }"
        : "=r"(a) : "l"(p));
    return a;
}
__device__ __forceinline__ void ldsm4(uint32_t& r0, uint32_t& r1,
                                      uint32_t& r2, uint32_t& r3,
                                      uint32_t addr) {
    asm volatile("ldmatrix.sync.aligned.m8n8.x4.shared.b16 {%0,%1,%2,%3}, [%4];"
                 : "=r"(r0), "=r"(r1), "=r"(r2), "=r"(r3) : "r"(addr));
}
__device__ __forceinline__ void mma16816(float* d, const uint32_t* a,
                                         const uint32_t* b) {
    asm volatile(
        "mma.sync.aligned.m16n8k16.row.col.f32.bf16.bf16.f32 "
        "{%0,%1,%2,%3}, {%4,%5,%6,%7}, {%8,%9}, {%0,%1,%2,%3};"
        : "+f"(d[0]), "+f"(d[1]), "+f"(d[2]), "+f"(d[3])
        : "r"(a[0]), "r"(a[1]), "r"(a[2]), "r"(a[3]), "r"(b[0]), "r"(b[1]));
}
#define CP_ASYNC16(dst, src) \
    asm volatile("cp.async.cg.shared.global [%0], [%1], 16;" :: "r"(dst), "l"(src))
#define CP_COMMIT() asm volatile("cp.async.commit_group;" ::: "memory")
#define CP_WAIT(n)  asm volatile("cp.async.wait_group %0;" :: "n"(n) : "memory")

__device__ __forceinline__ void split4(float4 v, uint2& hi, uint2& lo) {
    __nv_bfloat16 h0 = __float2bfloat16_rn(v.x), h1 = __float2bfloat16_rn(v.y);
    __nv_bfloat16 h2 = __float2bfloat16_rn(v.z), h3 = __float2bfloat16_rn(v.w);
    float r0 = v.x - __bfloat162float(h0), r1 = v.y - __bfloat162float(h1);
    float r2 = v.z - __bfloat162float(h2), r3 = v.w - __bfloat162float(h3);
    __nv_bfloat16 l0 = __float2bfloat16_rn(r0), l1 = __float2bfloat16_rn(r1);
    __nv_bfloat16 l2 = __float2bfloat16_rn(r2), l3 = __float2bfloat16_rn(r3);
    hi.x = ((uint32_t)__bfloat16_as_ushort(h1) << 16) | __bfloat16_as_ushort(h0);
    hi.y = ((uint32_t)__bfloat16_as_ushort(h3) << 16) | __bfloat16_as_ushort(h2);
    lo.x = ((uint32_t)__bfloat16_as_ushort(l1) << 16) | __bfloat16_as_ushort(l0);
    lo.y = ((uint32_t)__bfloat16_as_ushort(l3) << 16) | __bfloat16_as_ushort(l2);
}

// ============================================================
// prep kernels
// ============================================================
__global__ __launch_bounds__(256) void split_fp32(
    const float* __restrict__ X, __nv_bfloat16* __restrict__ Xh,
    __nv_bfloat16* __restrict__ Xl)
{
    int i = blockIdx.x * 256 + threadIdx.x;   // over float4s
    float4 v = ((const float4*)X)[i];
    uint2 hi, lo;
    split4(v, hi, lo);
    ((uint2*)Xh)[i] = hi;
    ((uint2*)Xl)[i] = lo;
}

// transpose + split: Th/Tl[rowoff + n][k] = split(W[k][n])
__global__ __launch_bounds__(256) void transpose_split(
    const float* __restrict__ W, __nv_bfloat16* __restrict__ Th,
    __nv_bfloat16* __restrict__ Tl, int rowoff)
{
    __shared__ float t[32][33];
    int bx = blockIdx.x * 32, by = blockIdx.y * 32;
    int x = threadIdx.x & 31, y = threadIdx.x >> 5;
    for (int i = y; i < 32; i += 8) t[i][x] = W[(size_t)(by + i) * DD + bx + x];
    __syncthreads();
    for (int i = y; i < 32; i += 8) {
        float v = t[x][i];
        __nv_bfloat16 h = __float2bfloat16_rn(v);
        __nv_bfloat16 l = __float2bfloat16_rn(v - __bfloat162float(h));
        size_t o = (size_t)(rowoff + bx + i) * DD + by + x;
        Th[o] = h;
        Tl[o] = l;
    }
}

__global__ void concat_bias(const float* bq, const float* bk, const float* bv,
                            float* bout)
{
    int i = blockIdx.x * 256 + threadIdx.x;
    if (i < DD) bout[i] = bq[i];
    else if (i < 2 * DD) bout[i] = bk[i - DD];
    else if (i < 3 * DD) bout[i] = bv[i - 2 * DD];
}

// ============================================================
// Tensor-core bf16 3-pass split GEMM, cp.async 3-stage pipeline.
// A given as preformatted hi/lo bf16 [M,512]; B as hi/lo bf16 rows [n][k].
// Tile 128x128, BK=32, 8 warps (4x2), warp tile 32x64.
// smem tile: 128 rows x 80B (32 bf16 cols padded) -> conflict-free ldmatrix.
// Output select: sel=bn>>2 -> o0/o1/o2; col=(bn&3)*128; bias index bn*128.
// ============================================================
#define BKC 32
#define NKCH (DD / BKC)          // 16
#define ROWB 80
#define TILEB (128 * ROWB)       // 10240
#define ST_AHI 0
#define ST_ALO (1 * TILEB)
#define ST_BHI (2 * TILEB)
#define ST_BLO (3 * TILEB)
#define STAGEB (4 * TILEB)       // 40960
#define PIPE 3
#define GEMM_SMEM (PIPE * STAGEB)  // 122880
#define OFF80(row, ch) ((uint32_t)((row) * ROWB + ((ch) << 4)))

__global__ __launch_bounds__(256, 1) void mma_gemm(
    const __nv_bfloat16* __restrict__ Ahi, const __nv_bfloat16* __restrict__ Alo,
    const __nv_bfloat16* __restrict__ Bhi, const __nv_bfloat16* __restrict__ Blo,
    const float* __restrict__ bias,
    float* __restrict__ o0, float* __restrict__ o1, float* __restrict__ o2)
{
    extern __shared__ char smem[];
    const uint32_t sb = smem_to_u32(smem);

    const int tid = threadIdx.x;
    const int wid = tid >> 5, lane = tid & 31;
    const int bn = blockIdx.x, bm = blockIdx.y;
    const int warp_m = wid >> 1, warp_n = wid & 1;

    const __nv_bfloat16* Ahi_b = Ahi + (size_t)bm * 128 * DD;
    const __nv_bfloat16* Alo_b = Alo + (size_t)bm * 128 * DD;
    const __nv_bfloat16* Bhi_b = Bhi + (size_t)bn * 128 * DD;
    const __nv_bfloat16* Blo_b = Blo + (size_t)bn * 128 * DD;

    // loader: 2 16B-units per tile per thread
    const int u0row = tid >> 2, u0ch = tid & 3;
    const int u1row = (tid + 256) >> 2, u1ch = tid & 3;  // +256 = +64 rows

    auto load_chunk = [&](int c, int s) {
        const uint32_t stg = sb + s * STAGEB;
        const int k0 = c * BKC;
        {
            const size_t go = (size_t)u0row * DD + k0 + u0ch * 8;
            const uint32_t so = OFF80(u0row, u0ch);
            CP_ASYNC16(stg + ST_AHI + so, Ahi_b + go);
            CP_ASYNC16(stg + ST_ALO + so, Alo_b + go);
            CP_ASYNC16(stg + ST_BHI + so, Bhi_b + go);
            CP_ASYNC16(stg + ST_BLO + so, Blo_b + go);
        }
        {
            const size_t go = (size_t)u1row * DD + k0 + u1ch * 8;
            const uint32_t so = OFF80(u1row, u1ch);
            CP_ASYNC16(stg + ST_AHI + so, Ahi_b + go);
            CP_ASYNC16(stg + ST_ALO + so, Alo_b + go);
            CP_ASYNC16(stg + ST_BHI + so, Bhi_b + go);
            CP_ASYNC16(stg + ST_BLO + so, Blo_b + go);
        }
    };

    float acc[2][8][4];
#pragma unroll
    for (int i = 0; i < 2; i++)
#pragma unroll
        for (int j = 0; j < 8; j++)
#pragma unroll
            for (int e = 0; e < 4; e++) acc[i][j][e] = 0.f;

    // ldmatrix lane-address components
    const int mat = lane >> 3, mr = lane & 7;
    const int a_row_b = warp_m * 32 + (mat & 1) * 8 + mr;   // + im*16
    const int b_row_b = warp_n * 64 + (mat & 1) * 8 + mr;   // + j16*16
    const int mchunk = mat >> 1;                            // + kk*2

    load_chunk(0, 0);
    CP_COMMIT();
    load_chunk(1, 1);
    CP_COMMIT();

    for (int c = 0; c < NKCH; c++) {
        CP_WAIT(1);
        __syncthreads();
        if (c + 2 < NKCH) {
            load_chunk(c + 2, (c + 2) % PIPE);
            CP_COMMIT();
        }

        const uint32_t stg = sb + (c % PIPE) * STAGEB;
#pragma unroll
        for (int kk = 0; kk < 2; kk++) {
            const int ch = kk * 2 + mchunk;
            uint32_t ahi[2][4], alo[2][4], bhi[8][2], blo[8][2];
#pragma unroll
            for (int im = 0; im < 2; im++) {
                const int row = a_row_b + im * 16;
                ldsm4(ahi[im][0], ahi[im][1], ahi[im][2], ahi[im][3],
                      stg + ST_AHI + OFF80(row, ch));
                ldsm4(alo[im][0], alo[im][1], alo[im][2], alo[im][3],
                      stg + ST_ALO + OFF80(row, ch));
            }
#pragma unroll
            for (int j16 = 0; j16 < 4; j16++) {
                const int row = b_row_b + j16 * 16;
                uint32_t r0, r1, r2, r3;
                ldsm4(r0, r1, r2, r3, stg + ST_BHI + OFF80(row, ch));
                bhi[j16 * 2][0] = r0; bhi[j16 * 2][1] = r2;
                bhi[j16 * 2 + 1][0] = r1; bhi[j16 * 2 + 1][1] = r3;
                ldsm4(r0, r1, r2, r3, stg + ST_BLO + OFF80(row, ch));
                blo[j16 * 2][0] = r0; blo[j16 * 2][1] = r2;
                blo[j16 * 2 + 1][0] = r1; blo[j16 * 2 + 1][1] = r3;
            }
#pragma unroll
            for (int im = 0; im < 2; im++)
#pragma unroll
                for (int t = 0; t < 8; t++) {
                    mma16816(acc[im][t], ahi[im], bhi[t]);
                    mma16816(acc[im][t], ahi[im], blo[t]);
                    mma16816(acc[im][t], alo[im], bhi[t]);
                }
        }
        __syncthreads();
    }

    // ---- epilogue ----
    const int sel = bn >> 2;
    float* C = sel == 0 ? o0 : (sel == 1 ? o1 : o2);
    const int erow = lane >> 2, ecol = (lane & 3) * 2;
#pragma unroll
    for (int im = 0; im < 2; im++) {
        const size_t row0 = (size_t)bm * 128 + warp_m * 32 + im * 16 + erow;
#pragma unroll
        for (int t = 0; t < 8; t++) {
            const int cofs = warp_n * 64 + t * 8 + ecol;
            const int col = (bn & 3) * 128 + cofs;
            float2 b2 = *(const float2*)&bias[bn * 128 + cofs];
            float2 q0 = make_float2(acc[im][t][0] + b2.x, acc[im][t][1] + b2.y);
            float2 q1 = make_float2(acc[im][t][2] + b2.x, acc[im][t][3] + b2.y);
            *(float2*)&C[row0 * DD + col] = q0;
            *(float2*)&C[(row0 + 8) * DD + col] = q1;
        }
    }
}

// ============================================================
// Sketch: z = gamma*Z + beta; u=z@G1, w=z@G2, phi=((1/8)u*w)^2
// ============================================================
__global__ __launch_bounds__(256) void sketch_kernel(
    const float* __restrict__ Z,
    const float* __restrict__ G1, const float* __restrict__ G2,
    const float* __restrict__ gamma, const float* __restrict__ beta,
    float* __restrict__ phi)
{
    __shared__ float Zs[64][64];
    __shared__ float G1s[64 * 64];
    __shared__ float G2s[64 * 64];

    const int tid = threadIdx.x;
    const int h = blockIdx.y;
    const int row0 = blockIdx.x * 64;

    for (int i = tid; i < 1024; i += 256) {
        ((float4*)G1s)[i] = ((const float4*)G1)[i];
        ((float4*)G2s)[i] = ((const float4*)G2)[i];
    }
    const float g0 = gamma[0], b0 = beta[0];
    for (int i = tid; i < 1024; i += 256) {
        int r = i >> 4;
        int c4 = (i & 15) * 4;
        float4 z = *(const float4*)&Z[(size_t)(row0 + r) * DD + h * HDIM + c4];
        z.x = g0 * z.x + b0;
        z.y = g0 * z.y + b0;
        z.z = g0 * z.z + b0;
        z.w = g0 * z.w + b0;
        *(float4*)&Zs[r][c4] = z;
    }
    __syncthreads();

    const int tr = tid >> 4, tc = tid & 15;
    const int r0 = tr * 4, c0 = tc * 4;
    float au[4][4], aw[4][4];
#pragma unroll
    for (int i = 0; i < 4; i++)
#pragma unroll
        for (int j = 0; j < 4; j++) { au[i][j] = 0.f; aw[i][j] = 0.f; }

#pragma unroll 8
    for (int hd = 0; hd < 64; hd++) {
        float4 g1 = *(float4*)&G1s[hd * 64 + c0];
        float4 g2 = *(float4*)&G2s[hd * 64 + c0];
#pragma unroll
        for (int i = 0; i < 4; i++) {
            float z = Zs[r0 + i][hd];
            au[i][0] += z * g1.x; au[i][1] += z * g1.y;
            au[i][2] += z * g1.z; au[i][3] += z * g1.w;
            aw[i][0] += z * g2.x; aw[i][1] += z * g2.y;
            aw[i][2] += z * g2.z; aw[i][3] += z * g2.w;
        }
    }

    const int b = row0 / SS;
    const int sbase = row0 % SS;
    const float inv = 0.125f;
#pragma unroll
    for (int i = 0; i < 4; i++) {
        int s = sbase + r0 + i;
        float h0 = inv * au[i][0] * aw[i][0];
        float h1 = inv * au[i][1] * aw[i][1];
        float h2 = inv * au[i][2] * aw[i][2];
        float h3 = inv * au[i][3] * aw[i][3];
        float4 o = make_float4(h0 * h0, h1 * h1, h2 * h2, h3 * h3);
        *(float4*)&phi[(((size_t)b * HH + h) * SS + s) * RR + c0] = o;
    }
}

// ============================================================
// kv partial sums over S chunks
// ============================================================
__global__ __launch_bounds__(256) void kvsum_kernel(
    const float* __restrict__ phik, const float* __restrict__ v,
    float* __restrict__ kvp, float* __restrict__ ksp)
{
    const int bh = blockIdx.y;
    const int chunk = blockIdx.x;
    const int b = bh >> 3, h = bh & 7;
    const int CS = SS / NCHUNK;

    __shared__ float Ps[32][64];
    __shared__ float Vs[32][64];

    const int tid = threadIdx.x;
    const int tr = tid >> 4, tc = tid & 15;
    const int r0 = tr * 4, d0 = tc * 4;

    float acc[4][4];
#pragma unroll
    for (int i = 0; i < 4; i++)
#pragma unroll
        for (int j = 0; j < 4; j++) acc[i][j] = 0.f;
    float ks = 0.f;

    const int s0 = chunk * CS;
    for (int st = 0; st < CS; st += 32) {
        for (int i = tid; i < 512; i += 256) {
            int row = i >> 4;
            int c4 = (i & 15) * 4;
            *(float4*)&Ps[row][c4] =
                *(const float4*)&phik[((size_t)bh * SS + s0 + st + row) * RR + c4];
            *(float4*)&Vs[row][c4] =
                *(const float4*)&v[((size_t)b * SS + s0 + st + row) * DD + h * HDIM + c4];
        }
        __syncthreads();
#pragma unroll 8
        for (int ss = 0; ss < 32; ss++) {
            float4 p = *(float4*)&Ps[ss][r0];
            float4 vv = *(float4*)&Vs[ss][d0];
            acc[0][0] += p.x * vv.x; acc[0][1] += p.x * vv.y;
            acc[0][2] += p.x * vv.z; acc[0][3] += p.x * vv.w;
            acc[1][0] += p.y * vv.x; acc[1][1] += p.y * vv.y;
            acc[1][2] += p.y * vv.z; acc[1][3] += p.y * vv.w;
            acc[2][0] += p.z * vv.x; acc[2][1] += p.z * vv.y;
            acc[2][2] += p.z * vv.z; acc[2][3] += p.z * vv.w;
            acc[3][0] += p.w * vv.x; acc[3][1] += p.w * vv.y;
            acc[3][2] += p.w * vv.z; acc[3][3] += p.w * vv.w;
        }
        if (tid < 64) {
#pragma unroll
            for (int ss = 0; ss < 32; ss++) ks += Ps[ss][tid];
        }
        __syncthreads();
    }

    float* kvout = kvp + ((size_t)bh * NCHUNK + chunk) * (RR * HDIM);
#pragma unroll
    for (int i = 0; i < 4; i++)
        *(float4*)&kvout[(r0 + i) * HDIM + d0] =
            make_float4(acc[i][0], acc[i][1], acc[i][2], acc[i][3]);
    if (tid < 64) ksp[((size_t)bh * NCHUNK + chunk) * RR + tid] = ks;
}

__global__ void reduce_kernel(const float* __restrict__ kvp,
                              const float* __restrict__ ksp,
                              float* __restrict__ kv, float* __restrict__ ks)
{
    const int idx = blockIdx.x * 256 + threadIdx.x;
    const int total_kv = BB * HH * RR * HDIM;
    if (idx < total_kv) {
        int bh = idx >> 12, e = idx & 4095;
        float s = 0.f;
#pragma unroll
        for (int c = 0; c < NCHUNK; c++)
            s += kvp[((size_t)bh * NCHUNK + c) * 4096 + e];
        kv[idx] = s;
    } else if (idx < total_kv + BB * HH * RR) {
        int j = idx - total_kv;
        int bh = j >> 6, r = j & 63;
        float s = 0.f;
#pragma unroll
        for (int c = 0; c < NCHUNK; c++)
            s += ksp[((size_t)bh * NCHUNK + c) * RR + r];
        ks[j] = s;
    }
}

// ============================================================
// attn output -> split bf16 hi/lo (feeds final GEMM directly)
// ============================================================
__global__ __launch_bounds__(256) void attn_out_kernel(
    const float* __restrict__ phiq, const float* __restrict__ kv,
    const float* __restrict__ ks,
    __nv_bfloat16* __restrict__ ahi, __nv_bfloat16* __restrict__ alo)
{
    const int bh = blockIdx.y;
    const int stile = blockIdx.x;
    const int b = bh >> 3, h = bh & 7;

    __shared__ float KVs[4096];
    __shared__ float KSs[64];
    __shared__ float Ps[32 * 65];
    __shared__ float Dens[32];

    const int tid = threadIdx.x;
    const int s0 = stile * 32;

    for (int i = tid; i < 1024; i += 256)
        ((float4*)KVs)[i] = ((const float4*)(kv + (size_t)bh * 4096))[i];
    if (tid < 64) KSs[tid] = ks[bh * RR + tid];
    for (int i = tid; i < 2048; i += 256) {
        int row = i >> 6, c = i & 63;
        Ps[row * 65 + c] = phiq[((size_t)bh * SS + s0 + row) * RR + c];
    }
    __syncthreads();

    if (tid < 32) {
        float dsum = 0.f;
#pragma unroll
        for (int r = 0; r < 64; r++) dsum += Ps[tid * 65 + r] * KSs[r];
        Dens[tid] = dsum + 1e-6f;
    }
    __syncthreads();

    const int d = tid & 63, g = tid >> 6;
    for (int rr = g; rr < 32; rr += 4) {
        float num = 0.f;
#pragma unroll
        for (int r = 0; r < 64; r++) num += Ps[rr * 65 + r] * KVs[r * 64 + d];
        float o = num / Dens[rr];
        __nv_bfloat16 hi = __float2bfloat16_rn(o);
        __nv_bfloat16 lo = __float2bfloat16_rn(o - __bfloat162float(hi));
        size_t idx = ((size_t)b * SS + s0 + rr) * DD + h * HDIM + d;
        ahi[idx] = hi;
        alo[idx] = lo;
    }
}

// ============================================================
// launch
// ============================================================
extern "C" void kernel_launch(void* const* d_in, const int* in_sizes, int n_in,
                              void* d_out, int out_size)
{
    const float* x       = (const float*)d_in[0];
    const float* Wq      = (const float*)d_in[1];
    const float* bq      = (const float*)d_in[2];
    const float* Wk      = (const float*)d_in[3];
    const float* bk      = (const float*)d_in[4];
    const float* Wv      = (const float*)d_in[5];
    const float* bv      = (const float*)d_in[6];
    const float* Wp      = (const float*)d_in[7];
    const float* bp      = (const float*)d_in[8];
    const float* gamma_q = (const float*)d_in[9];
    const float* beta_q  = (const float*)d_in[10];
    const float* gamma_k = (const float*)d_in[11];
    const float* beta_k  = (const float*)d_in[12];
    const float* qG1     = (const float*)d_in[13];
    const float* qG2     = (const float*)d_in[14];
    const float* kG1     = (const float*)d_in[15];
    const float* kG2     = (const float*)d_in[16];
    float* out = (float*)d_out;

    float *p_q, *p_k, *p_v, *p_phiq, *p_phik, *p_kvp, *p_ksp, *p_kv, *p_ks, *p_bqkv;
    __nv_bfloat16 *p_xhi, *p_xlo, *p_ahi, *p_alo, *p_wthi, *p_wtlo;
    cudaGetSymbolAddress((void**)&p_q, g_q);
    cudaGetSymbolAddress((void**)&p_k, g_k);
    cudaGetSymbolAddress((void**)&p_v, g_v);
    cudaGetSymbolAddress((void**)&p_phiq, g_phiq);
    cudaGetSymbolAddress((void**)&p_phik, g_phik);
    cudaGetSymbolAddress((void**)&p_kvp, g_kvp);
    cudaGetSymbolAddress((void**)&p_ksp, g_ksp);
    cudaGetSymbolAddress((void**)&p_kv, g_kv);
    cudaGetSymbolAddress((void**)&p_ks, g_ks);
    cudaGetSymbolAddress((void**)&p_bqkv, g_biasqkv);
    cudaGetSymbolAddress((void**)&p_xhi, g_xhi);
    cudaGetSymbolAddress((void**)&p_xlo, g_xlo);
    cudaGetSymbolAddress((void**)&p_ahi, g_ahi);
    cudaGetSymbolAddress((void**)&p_alo, g_alo);
    cudaGetSymbolAddress((void**)&p_wthi, g_wthi);
    cudaGetSymbolAddress((void**)&p_wtlo, g_wtlo);

    cudaFuncSetAttribute(mma_gemm, cudaFuncAttributeMaxDynamicSharedMemorySize,
                         GEMM_SMEM);

    // ---- prep: split x; transpose+split weights; concat bias ----
    split_fp32<<<BSROWS * DD / 4 / 256, 256>>>(x, p_xhi, p_xlo);
    dim3 tg(16, 16);
    transpose_split<<<tg, 256>>>(Wq, p_wthi, p_wtlo, 0);
    transpose_split<<<tg, 256>>>(Wk, p_wthi, p_wtlo, 512);
    transpose_split<<<tg, 256>>>(Wv, p_wthi, p_wtlo, 1024);
    transpose_split<<<tg, 256>>>(Wp, p_wthi, p_wtlo, 1536);
    concat_bias<<<6, 256>>>(bq, bk, bv, p_bqkv);

    // ---- fused QKV GEMM: grid (12, 256) ----
    dim3 gq(12, BSROWS / 128);
    mma_gemm<<<gq, 256, GEMM_SMEM>>>(p_xhi, p_xlo, p_wthi, p_wtlo, p_bqkv,
                                     p_q, p_k, p_v);

    dim3 sk_grid(BSROWS / 64, HH);
    sketch_kernel<<<sk_grid, 256>>>(p_q, qG1, qG2, gamma_q, beta_q, p_phiq);
    sketch_kernel<<<sk_grid, 256>>>(p_k, kG1, kG2, gamma_k, beta_k, p_phik);

    kvsum_kernel<<<dim3(NCHUNK, BB * HH), 256>>>(p_phik, p_v, p_kvp, p_ksp);

    int red_total = BB * HH * RR * HDIM + BB * HH * RR;
    reduce_kernel<<<(red_total + 255) / 256, 256>>>(p_kvp, p_ksp, p_kv, p_ks);

    attn_out_kernel<<<dim3(SS / 32, BB * HH), 256>>>(p_phiq, p_kv, p_ks,
                                                     p_ahi, p_alo);

    // ---- output projection: grid (4, 256) ----
    dim3 go(4, BSROWS / 128);
    mma_gemm<<<go, 256, GEMM_SMEM>>>(p_ahi, p_alo,
                                     p_wthi + 1536 * DD, p_wtlo + 1536 * DD,
                                     bp, out, out, out);
}

// round 5
// speedup vs baseline: 1.8470x; 1.0216x over previous
#include <cuda_runtime.h>
#include <cuda_bf16.h>
#include <cstdint>

// Problem constants
#define BB 4
#define SS 8192
#define DD 512
#define HH 8
#define HDIM 64
#define RR 64
#define BSROWS (BB * SS)      // 32768
#define NCHUNK 16

// -------- scratch (static device globals; no allocation) --------
__device__ float g_q[BSROWS * DD];
__device__ float g_k[BSROWS * DD];
__device__ float g_v[BSROWS * DD];
__device__ float g_phiq[BB * HH * SS * RR];
__device__ float g_phik[BB * HH * SS * RR];
__device__ float g_kvp[BB * HH * NCHUNK * RR * HDIM];
__device__ float g_ksp[BB * HH * NCHUNK * RR];
__device__ float g_kv[BB * HH * RR * HDIM];
__device__ float g_ks[BB * HH * RR];
__device__ __nv_bfloat16 g_xhi[BSROWS * DD];
__device__ __nv_bfloat16 g_xlo[BSROWS * DD];
__device__ __nv_bfloat16 g_ahi[BSROWS * DD];   // attn output hi
__device__ __nv_bfloat16 g_alo[BSROWS * DD];   // attn output lo
__device__ __nv_bfloat16 g_wthi[4 * DD * DD];  // [2048][512]: Wq^T,Wk^T,Wv^T,Wp^T
__device__ __nv_bfloat16 g_wtlo[4 * DD * DD];
__device__ float g_biasqkv[3 * DD];

// ============================================================
// helpers
// ============================================================
__device__ __forceinline__ uint32_t smem_to_u32(const void* p) {
    uint32_t a;
    asm("{ .reg .u64 t; cvta.to.shared.u64 t, %1; cvt.u32.u64 %0, t; }"
        : "=r"(a) : "l"(p));
    return a;
}
__device__ __forceinline__ void ldsm4(uint32_t& r0, uint32_t& r1,
                                      uint32_t& r2, uint32_t& r3,
                                      uint32_t addr) {
    asm volatile("ldmatrix.sync.aligned.m8n8.x4.shared.b16 {%0,%1,%2,%3}, [%4];"
                 : "=r"(r0), "=r"(r1), "=r"(r2), "=r"(r3) : "r"(addr));
}
__device__ __forceinline__ void mma16816(float* d, const uint32_t* a,
                                         const uint32_t* b) {
    asm volatile(
        "mma.sync.aligned.m16n8k16.row.col.f32.bf16.bf16.f32 "
        "{%0,%1,%2,%3}, {%4,%5,%6,%7}, {%8,%9}, {%0,%1,%2,%3};"
        : "+f"(d[0]), "+f"(d[1]), "+f"(d[2]), "+f"(d[3])
        : "r"(a[0]), "r"(a[1]), "r"(a[2]), "r"(a[3]), "r"(b[0]), "r"(b[1]));
}
#define CP_ASYNC16(dst, src) \
    asm volatile("cp.async.cg.shared.global [%0], [%1], 16;" :: "r"(dst), "l"(src))
#define CP_COMMIT() asm volatile("cp.async.commit_group;" ::: "memory")
#define CP_WAIT(n)  asm volatile("cp.async.wait_group %0;" :: "n"(n) : "memory")

__device__ __forceinline__ void split4(float4 v, uint2& hi, uint2& lo) {
    __nv_bfloat16 h0 = __float2bfloat16_rn(v.x), h1 = __float2bfloat16_rn(v.y);
    __nv_bfloat16 h2 = __float2bfloat16_rn(v.z), h3 = __float2bfloat16_rn(v.w);
    float r0 = v.x - __bfloat162float(h0), r1 = v.y - __bfloat162float(h1);
    float r2 = v.z - __bfloat162float(h2), r3 = v.w - __bfloat162float(h3);
    __nv_bfloat16 l0 = __float2bfloat16_rn(r0), l1 = __float2bfloat16_rn(r1);
    __nv_bfloat16 l2 = __float2bfloat16_rn(r2), l3 = __float2bfloat16_rn(r3);
    hi.x = ((uint32_t)__bfloat16_as_ushort(h1) << 16) | __bfloat16_as_ushort(h0);
    hi.y = ((uint32_t)__bfloat16_as_ushort(h3) << 16) | __bfloat16_as_ushort(h2);
    lo.x = ((uint32_t)__bfloat16_as_ushort(l1) << 16) | __bfloat16_as_ushort(l0);
    lo.y = ((uint32_t)__bfloat16_as_ushort(l3) << 16) | __bfloat16_as_ushort(l2);
}

// ============================================================
// prep kernels
// ============================================================
__global__ __launch_bounds__(256) void split_fp32(
    const float* __restrict__ X, __nv_bfloat16* __restrict__ Xh,
    __nv_bfloat16* __restrict__ Xl)
{
    int i = blockIdx.x * 256 + threadIdx.x;   // over float4s
    float4 v = ((const float4*)X)[i];
    uint2 hi, lo;
    split4(v, hi, lo);
    ((uint2*)Xh)[i] = hi;
    ((uint2*)Xl)[i] = lo;
}

// transpose + split: Th/Tl[rowoff + n][k] = split(W[k][n])
__global__ __launch_bounds__(256) void transpose_split(
    const float* __restrict__ W, __nv_bfloat16* __restrict__ Th,
    __nv_bfloat16* __restrict__ Tl, int rowoff)
{
    __shared__ float t[32][33];
    int bx = blockIdx.x * 32, by = blockIdx.y * 32;
    int x = threadIdx.x & 31, y = threadIdx.x >> 5;
    for (int i = y; i < 32; i += 8) t[i][x] = W[(size_t)(by + i) * DD + bx + x];
    __syncthreads();
    for (int i = y; i < 32; i += 8) {
        float v = t[x][i];
        __nv_bfloat16 h = __float2bfloat16_rn(v);
        __nv_bfloat16 l = __float2bfloat16_rn(v - __bfloat162float(h));
        size_t o = (size_t)(rowoff + bx + i) * DD + by + x;
        Th[o] = h;
        Tl[o] = l;
    }
}

__global__ void concat_bias(const float* bq, const float* bk, const float* bv,
                            float* bout)
{
    int i = blockIdx.x * 256 + threadIdx.x;
    if (i < DD) bout[i] = bq[i];
    else if (i < 2 * DD) bout[i] = bk[i - DD];
    else if (i < 3 * DD) bout[i] = bv[i - 2 * DD];
}

// ============================================================
// Tensor-core bf16 3-pass split GEMM, cp.async 3-stage pipeline.
// CTA tile 128x256, 8 warps (2m x 4n), warp tile 64x64.
// smem rows padded to 80B -> conflict-free ldmatrix.
// Output select: sel = bn>>1; column base = (bn&1)*256.
// ============================================================
#define BKC 32
#define NKCH (DD / BKC)          // 16
#define ROWB 80
#define TILE_A (128 * ROWB)      // 10240
#define TILE_B (256 * ROWB)      // 20480
#define ST_AHI 0
#define ST_ALO TILE_A
#define ST_BHI (2 * TILE_A)
#define ST_BLO (2 * TILE_A + TILE_B)
#define STAGEB (2 * TILE_A + 2 * TILE_B)   // 61440
#define PIPE 3
#define GEMM_SMEM (PIPE * STAGEB)          // 184320
#define OFF80(row, ch) ((uint32_t)((row) * ROWB + ((ch) << 4)))

__global__ __launch_bounds__(256, 1) void mma_gemm(
    const __nv_bfloat16* __restrict__ Ahi, const __nv_bfloat16* __restrict__ Alo,
    const __nv_bfloat16* __restrict__ Bhi, const __nv_bfloat16* __restrict__ Blo,
    const float* __restrict__ bias,
    float* __restrict__ o0, float* __restrict__ o1, float* __restrict__ o2)
{
    extern __shared__ char smem[];
    const uint32_t sb = smem_to_u32(smem);

    const int tid = threadIdx.x;
    const int wid = tid >> 5, lane = tid & 31;
    const int bn = blockIdx.x, bm = blockIdx.y;
    const int warp_m = wid & 1, warp_n = wid >> 1;

    const __nv_bfloat16* Ahi_b = Ahi + (size_t)bm * 128 * DD;
    const __nv_bfloat16* Alo_b = Alo + (size_t)bm * 128 * DD;
    const __nv_bfloat16* Bhi_b = Bhi + (size_t)bn * 256 * DD;
    const __nv_bfloat16* Blo_b = Blo + (size_t)bn * 256 * DD;

    // loader: row = tid>>2 (0..63), ch = tid&3
    const int lrow = tid >> 2;
    const int lch = tid & 3;

    auto load_chunk = [&](int c, int s) {
        const uint32_t stg = sb + s * STAGEB;
        const int k0 = c * BKC;
#pragma unroll
        for (int sw = 0; sw < 2; sw++) {
            const int row = sw * 64 + lrow;
            const size_t go = (size_t)row * DD + k0 + lch * 8;
            const uint32_t so = OFF80(row, lch);
            CP_ASYNC16(stg + ST_AHI + so, Ahi_b + go);
            CP_ASYNC16(stg + ST_ALO + so, Alo_b + go);
        }
#pragma unroll
        for (int sw = 0; sw < 4; sw++) {
            const int row = sw * 64 + lrow;
            const size_t go = (size_t)row * DD + k0 + lch * 8;
            const uint32_t so = OFF80(row, lch);
            CP_ASYNC16(stg + ST_BHI + so, Bhi_b + go);
            CP_ASYNC16(stg + ST_BLO + so, Blo_b + go);
        }
    };

    float acc[4][8][4];
#pragma unroll
    for (int i = 0; i < 4; i++)
#pragma unroll
        for (int j = 0; j < 8; j++)
#pragma unroll
            for (int e = 0; e < 4; e++) acc[i][j][e] = 0.f;

    // ldmatrix lane-address components
    const int mat = lane >> 3, mr = lane & 7;
    const int a_row_b = warp_m * 64 + (mat & 1) * 8 + mr;   // + im*16
    const int b_row_b = warp_n * 64 + (mat & 1) * 8 + mr;   // + j16*16
    const int mchunk = mat >> 1;                            // + kk*2

    load_chunk(0, 0);
    CP_COMMIT();
    load_chunk(1, 1);
    CP_COMMIT();

    for (int c = 0; c < NKCH; c++) {
        CP_WAIT(1);
        __syncthreads();
        if (c + 2 < NKCH) {
            load_chunk(c + 2, (c + 2) % PIPE);
            CP_COMMIT();
        }

        const uint32_t stg = sb + (c % PIPE) * STAGEB;
#pragma unroll
        for (int kk = 0; kk < 2; kk++) {
            const int ch = kk * 2 + mchunk;
            uint32_t ahi[4][4], alo[4][4];
#pragma unroll
            for (int im = 0; im < 4; im++) {
                const int row = a_row_b + im * 16;
                ldsm4(ahi[im][0], ahi[im][1], ahi[im][2], ahi[im][3],
                      stg + ST_AHI + OFF80(row, ch));
                ldsm4(alo[im][0], alo[im][1], alo[im][2], alo[im][3],
                      stg + ST_ALO + OFF80(row, ch));
            }
#pragma unroll
            for (int j16 = 0; j16 < 4; j16++) {
                const int row = b_row_b + j16 * 16;
                uint32_t h0, h1, h2, h3, l0, l1, l2, l3;
                ldsm4(h0, h1, h2, h3, stg + ST_BHI + OFF80(row, ch));
                ldsm4(l0, l1, l2, l3, stg + ST_BLO + OFF80(row, ch));
                uint32_t bh0[2] = {h0, h2}, bh1[2] = {h1, h3};
                uint32_t bl0[2] = {l0, l2}, bl1[2] = {l1, l3};
#pragma unroll
                for (int im = 0; im < 4; im++) {
                    mma16816(acc[im][j16 * 2], ahi[im], bh0);
                    mma16816(acc[im][j16 * 2], ahi[im], bl0);
                    mma16816(acc[im][j16 * 2], alo[im], bh0);
                    mma16816(acc[im][j16 * 2 + 1], ahi[im], bh1);
                    mma16816(acc[im][j16 * 2 + 1], ahi[im], bl1);
                    mma16816(acc[im][j16 * 2 + 1], alo[im], bh1);
                }
            }
        }
    }

    // ---- epilogue ----
    const int sel = bn >> 1;
    float* C = sel == 0 ? o0 : (sel == 1 ? o1 : o2);
    const int colbase = (bn & 1) * 256;
    const int erow = lane >> 2, ecol = (lane & 3) * 2;
#pragma unroll
    for (int im = 0; im < 4; im++) {
        const size_t row0 = (size_t)bm * 128 + warp_m * 64 + im * 16 + erow;
#pragma unroll
        for (int t = 0; t < 8; t++) {
            const int cofs = warp_n * 64 + t * 8 + ecol;
            float2 b2 = *(const float2*)&bias[bn * 256 + cofs];
            float2 q0 = make_float2(acc[im][t][0] + b2.x, acc[im][t][1] + b2.y);
            float2 q1 = make_float2(acc[im][t][2] + b2.x, acc[im][t][3] + b2.y);
            *(float2*)&C[row0 * DD + colbase + cofs] = q0;
            *(float2*)&C[(row0 + 8) * DD + colbase + cofs] = q1;
        }
    }
}

// ============================================================
// Sketch: z = gamma*Z + beta; u=z@G1, w=z@G2, phi=((1/8)u*w)^2
// ============================================================
__global__ __launch_bounds__(256) void sketch_kernel(
    const float* __restrict__ Z,
    const float* __restrict__ G1, const float* __restrict__ G2,
    const float* __restrict__ gamma, const float* __restrict__ beta,
    float* __restrict__ phi)
{
    __shared__ float Zs[64][64];
    __shared__ float G1s[64 * 64];
    __shared__ float G2s[64 * 64];

    const int tid = threadIdx.x;
    const int h = blockIdx.y;
    const int row0 = blockIdx.x * 64;

    for (int i = tid; i < 1024; i += 256) {
        ((float4*)G1s)[i] = ((const float4*)G1)[i];
        ((float4*)G2s)[i] = ((const float4*)G2)[i];
    }
    const float g0 = gamma[0], b0 = beta[0];
    for (int i = tid; i < 1024; i += 256) {
        int r = i >> 4;
        int c4 = (i & 15) * 4;
        float4 z = *(const float4*)&Z[(size_t)(row0 + r) * DD + h * HDIM + c4];
        z.x = g0 * z.x + b0;
        z.y = g0 * z.y + b0;
        z.z = g0 * z.z + b0;
        z.w = g0 * z.w + b0;
        *(float4*)&Zs[r][c4] = z;
    }
    __syncthreads();

    const int tr = tid >> 4, tc = tid & 15;
    const int r0 = tr * 4, c0 = tc * 4;
    float au[4][4], aw[4][4];
#pragma unroll
    for (int i = 0; i < 4; i++)
#pragma unroll
        for (int j = 0; j < 4; j++) { au[i][j] = 0.f; aw[i][j] = 0.f; }

#pragma unroll 8
    for (int hd = 0; hd < 64; hd++) {
        float4 g1 = *(float4*)&G1s[hd * 64 + c0];
        float4 g2 = *(float4*)&G2s[hd * 64 + c0];
#pragma unroll
        for (int i = 0; i < 4; i++) {
            float z = Zs[r0 + i][hd];
            au[i][0] += z * g1.x; au[i][1] += z * g1.y;
            au[i][2] += z * g1.z; au[i][3] += z * g1.w;
            aw[i][0] += z * g2.x; aw[i][1] += z * g2.y;
            aw[i][2] += z * g2.z; aw[i][3] += z * g2.w;
        }
    }

    const int b = row0 / SS;
    const int sbase = row0 % SS;
    const float inv = 0.125f;
#pragma unroll
    for (int i = 0; i < 4; i++) {
        int s = sbase + r0 + i;
        float h0 = inv * au[i][0] * aw[i][0];
        float h1 = inv * au[i][1] * aw[i][1];
        float h2 = inv * au[i][2] * aw[i][2];
        float h3 = inv * au[i][3] * aw[i][3];
        float4 o = make_float4(h0 * h0, h1 * h1, h2 * h2, h3 * h3);
        *(float4*)&phi[(((size_t)b * HH + h) * SS + s) * RR + c0] = o;
    }
}

// ============================================================
// kv partial sums over S chunks
// ============================================================
__global__ __launch_bounds__(256) void kvsum_kernel(
    const float* __restrict__ phik, const float* __restrict__ v,
    float* __restrict__ kvp, float* __restrict__ ksp)
{
    const int bh = blockIdx.y;
    const int chunk = blockIdx.x;
    const int b = bh >> 3, h = bh & 7;
    const int CS = SS / NCHUNK;

    __shared__ float Ps[32][64];
    __shared__ float Vs[32][64];

    const int tid = threadIdx.x;
    const int tr = tid >> 4, tc = tid & 15;
    const int r0 = tr * 4, d0 = tc * 4;

    float acc[4][4];
#pragma unroll
    for (int i = 0; i < 4; i++)
#pragma unroll
        for (int j = 0; j < 4; j++) acc[i][j] = 0.f;
    float ks = 0.f;

    const int s0 = chunk * CS;
    for (int st = 0; st < CS; st += 32) {
        for (int i = tid; i < 512; i += 256) {
            int row = i >> 4;
            int c4 = (i & 15) * 4;
            *(float4*)&Ps[row][c4] =
                *(const float4*)&phik[((size_t)bh * SS + s0 + st + row) * RR + c4];
            *(float4*)&Vs[row][c4] =
                *(const float4*)&v[((size_t)b * SS + s0 + st + row) * DD + h * HDIM + c4];
        }
        __syncthreads();
#pragma unroll 8
        for (int ss = 0; ss < 32; ss++) {
            float4 p = *(float4*)&Ps[ss][r0];
            float4 vv = *(float4*)&Vs[ss][d0];
            acc[0][0] += p.x * vv.x; acc[0][1] += p.x * vv.y;
            acc[0][2] += p.x * vv.z; acc[0][3] += p.x * vv.w;
            acc[1][0] += p.y * vv.x; acc[1][1] += p.y * vv.y;
            acc[1][2] += p.y * vv.z; acc[1][3] += p.y * vv.w;
            acc[2][0] += p.z * vv.x; acc[2][1] += p.z * vv.y;
            acc[2][2] += p.z * vv.z; acc[2][3] += p.z * vv.w;
            acc[3][0] += p.w * vv.x; acc[3][1] += p.w * vv.y;
            acc[3][2] += p.w * vv.z; acc[3][3] += p.w * vv.w;
        }
        if (tid < 64) {
#pragma unroll
            for (int ss = 0; ss < 32; ss++) ks += Ps[ss][tid];
        }
        __syncthreads();
    }

    float* kvout = kvp + ((size_t)bh * NCHUNK + chunk) * (RR * HDIM);
#pragma unroll
    for (int i = 0; i < 4; i++)
        *(float4*)&kvout[(r0 + i) * HDIM + d0] =
            make_float4(acc[i][0], acc[i][1], acc[i][2], acc[i][3]);
    if (tid < 64) ksp[((size_t)bh * NCHUNK + chunk) * RR + tid] = ks;
}

__global__ void reduce_kernel(const float* __restrict__ kvp,
                              const float* __restrict__ ksp,
                              float* __restrict__ kv, float* __restrict__ ks)
{
    const int idx = blockIdx.x * 256 + threadIdx.x;
    const int total_kv = BB * HH * RR * HDIM;
    if (idx < total_kv) {
        int bh = idx >> 12, e = idx & 4095;
        float s = 0.f;
#pragma unroll
        for (int c = 0; c < NCHUNK; c++)
            s += kvp[((size_t)bh * NCHUNK + c) * 4096 + e];
        kv[idx] = s;
    } else if (idx < total_kv + BB * HH * RR) {
        int j = idx - total_kv;
        int bh = j >> 6, r = j & 63;
        float s = 0.f;
#pragma unroll
        for (int c = 0; c < NCHUNK; c++)
            s += ksp[((size_t)bh * NCHUNK + c) * RR + r];
        ks[j] = s;
    }
}

// ============================================================
// attn output -> split bf16 hi/lo (feeds final GEMM directly)
// ============================================================
__global__ __launch_bounds__(256) void attn_out_kernel(
    const float* __restrict__ phiq, const float* __restrict__ kv,
    const float* __restrict__ ks,
    __nv_bfloat16* __restrict__ ahi, __nv_bfloat16* __restrict__ alo)
{
    const int bh = blockIdx.y;
    const int stile = blockIdx.x;
    const int b = bh >> 3, h = bh & 7;

    __shared__ float KVs[4096];
    __shared__ float KSs[64];
    __shared__ float Ps[32 * 65];
    __shared__ float Dens[32];

    const int tid = threadIdx.x;
    const int s0 = stile * 32;

    for (int i = tid; i < 1024; i += 256)
        ((float4*)KVs)[i] = ((const float4*)(kv + (size_t)bh * 4096))[i];
    if (tid < 64) KSs[tid] = ks[bh * RR + tid];
    for (int i = tid; i < 2048; i += 256) {
        int row = i >> 6, c = i & 63;
        Ps[row * 65 + c] = phiq[((size_t)bh * SS + s0 + row) * RR + c];
    }
    __syncthreads();

    if (tid < 32) {
        float dsum = 0.f;
#pragma unroll
        for (int r = 0; r < 64; r++) dsum += Ps[tid * 65 + r] * KSs[r];
        Dens[tid] = dsum + 1e-6f;
    }
    __syncthreads();

    const int d = tid & 63, g = tid >> 6;
    for (int rr = g; rr < 32; rr += 4) {
        float num = 0.f;
#pragma unroll
        for (int r = 0; r < 64; r++) num += Ps[rr * 65 + r] * KVs[r * 64 + d];
        float o = num / Dens[rr];
        __nv_bfloat16 hi = __float2bfloat16_rn(o);
        __nv_bfloat16 lo = __float2bfloat16_rn(o - __bfloat162float(hi));
        size_t idx = ((size_t)b * SS + s0 + rr) * DD + h * HDIM + d;
        ahi[idx] = hi;
        alo[idx] = lo;
    }
}

// ============================================================
// launch
// ============================================================
extern "C" void kernel_launch(void* const* d_in, const int* in_sizes, int n_in,
                              void* d_out, int out_size)
{
    const float* x       = (const float*)d_in[0];
    const float* Wq      = (const float*)d_in[1];
    const float* bq      = (const float*)d_in[2];
    const float* Wk      = (const float*)d_in[3];
    const float* bk      = (const float*)d_in[4];
    const float* Wv      = (const float*)d_in[5];
    const float* bv      = (const float*)d_in[6];
    const float* Wp      = (const float*)d_in[7];
    const float* bp      = (const float*)d_in[8];
    const float* gamma_q = (const float*)d_in[9];
    const float* beta_q  = (const float*)d_in[10];
    const float* gamma_k = (const float*)d_in[11];
    const float* beta_k  = (const float*)d_in[12];
    const float* qG1     = (const float*)d_in[13];
    const float* qG2     = (const float*)d_in[14];
    const float* kG1     = (const float*)d_in[15];
    const float* kG2     = (const float*)d_in[16];
    float* out = (float*)d_out;

    float *p_q, *p_k, *p_v, *p_phiq, *p_phik, *p_kvp, *p_ksp, *p_kv, *p_ks, *p_bqkv;
    __nv_bfloat16 *p_xhi, *p_xlo, *p_ahi, *p_alo, *p_wthi, *p_wtlo;
    cudaGetSymbolAddress((void**)&p_q, g_q);
    cudaGetSymbolAddress((void**)&p_k, g_k);
    cudaGetSymbolAddress((void**)&p_v, g_v);
    cudaGetSymbolAddress((void**)&p_phiq, g_phiq);
    cudaGetSymbolAddress((void**)&p_phik, g_phik);
    cudaGetSymbolAddress((void**)&p_kvp, g_kvp);
    cudaGetSymbolAddress((void**)&p_ksp, g_ksp);
    cudaGetSymbolAddress((void**)&p_kv, g_kv);
    cudaGetSymbolAddress((void**)&p_ks, g_ks);
    cudaGetSymbolAddress((void**)&p_bqkv, g_biasqkv);
    cudaGetSymbolAddress((void**)&p_xhi, g_xhi);
    cudaGetSymbolAddress((void**)&p_xlo, g_xlo);
    cudaGetSymbolAddress((void**)&p_ahi, g_ahi);
    cudaGetSymbolAddress((void**)&p_alo, g_alo);
    cudaGetSymbolAddress((void**)&p_wthi, g_wthi);
    cudaGetSymbolAddress((void**)&p_wtlo, g_wtlo);

    cudaFuncSetAttribute(mma_gemm, cudaFuncAttributeMaxDynamicSharedMemorySize,
                         GEMM_SMEM);

    // ---- prep: split x; transpose+split weights; concat bias ----
    split_fp32<<<BSROWS * DD / 4 / 256, 256>>>(x, p_xhi, p_xlo);
    dim3 tg(16, 16);
    transpose_split<<<tg, 256>>>(Wq, p_wthi, p_wtlo, 0);
    transpose_split<<<tg, 256>>>(Wk, p_wthi, p_wtlo, 512);
    transpose_split<<<tg, 256>>>(Wv, p_wthi, p_wtlo, 1024);
    transpose_split<<<tg, 256>>>(Wp, p_wthi, p_wtlo, 1536);
    concat_bias<<<6, 256>>>(bq, bk, bv, p_bqkv);

    // ---- fused QKV GEMM: grid (6, 256), each CTA does 128x256 ----
    dim3 gq(6, BSROWS / 128);
    mma_gemm<<<gq, 256, GEMM_SMEM>>>(p_xhi, p_xlo, p_wthi, p_wtlo, p_bqkv,
                                     p_q, p_k, p_v);

    dim3 sk_grid(BSROWS / 64, HH);
    sketch_kernel<<<sk_grid, 256>>>(p_q, qG1, qG2, gamma_q, beta_q, p_phiq);
    sketch_kernel<<<sk_grid, 256>>>(p_k, kG1, kG2, gamma_k, beta_k, p_phik);

    kvsum_kernel<<<dim3(NCHUNK, BB * HH), 256>>>(p_phik, p_v, p_kvp, p_ksp);

    int red_total = BB * HH * RR * HDIM + BB * HH * RR;
    reduce_kernel<<<(red_total + 255) / 256, 256>>>(p_kvp, p_ksp, p_kv, p_ks);

    attn_out_kernel<<<dim3(SS / 32, BB * HH), 256>>>(p_phiq, p_kv, p_ks,
                                                     p_ahi, p_alo);

    // ---- output projection: grid (2, 256) ----
    dim3 go(2, BSROWS / 128);
    mma_gemm<<<go, 256, GEMM_SMEM>>>(p_ahi, p_alo,
                                     p_wthi + 1536 * DD, p_wtlo + 1536 * DD,
                                     bp, out, out, out);
}